// round 3
// baseline (speedup 1.0000x reference)
#include <cuda_runtime.h>

#define BB 16
#define TT 1024
#define DD 512
#define TM 64
#define TN 128
#define BK 32
#define NTHREADS 256
#define NSPLIT 2

// Scratch (device globals -- no allocation allowed in kernel_launch)
__device__ float g_n[BB * TT * DD];           // normalized features, 32 MB
__device__ float g_S[NSPLIT][BB * TT];        // per-split partial neg-sums
__device__ float g_pos[BB * TT];              // sim[t, t+1]

// ---------------------------------------------------------------------------
// Kernel 1: row normalization. One block per (b,t) row, 128 threads * float4.
// ---------------------------------------------------------------------------
__global__ __launch_bounds__(128) void norm_kernel(const float* __restrict__ f) {
    int row = blockIdx.x;
    const float4* x = reinterpret_cast<const float4*>(f + (size_t)row * DD);
    float4 v = x[threadIdx.x];
    float ss = v.x * v.x + v.y * v.y + v.z * v.z + v.w * v.w;
#pragma unroll
    for (int o = 16; o; o >>= 1) ss += __shfl_xor_sync(0xffffffffu, ss, o);
    __shared__ float warpsum[4];
    if ((threadIdx.x & 31) == 0) warpsum[threadIdx.x >> 5] = ss;
    __syncthreads();
    float tot = warpsum[0] + warpsum[1] + warpsum[2] + warpsum[3];
    float inv = 1.0f / fmaxf(sqrtf(tot), 1e-8f);
    float4 o4 = make_float4(v.x * inv, v.y * inv, v.z * inv, v.w * inv);
    reinterpret_cast<float4*>(g_n + (size_t)row * DD)[threadIdx.x] = o4;
}

// ---------------------------------------------------------------------------
// Kernel 2: per-batch Gram tiles fused with exp-sum over negatives.
// Block: TM=64 anchors x (512 s-values for one split), 256 threads.
// Microtile 4x8. Bs columns interleaved (tx*4 | 64+tx*4) for conflict-free
// LDS.128 (each 8-lane phase covers a contiguous 128B of banks).
// ---------------------------------------------------------------------------
__global__ __launch_bounds__(NTHREADS) void sim_kernel() {
    const float INV_T = 1.0f / 0.07f;   // also the fixed logsumexp shift M

    int tile  = blockIdx.x;   // 0..15 anchor tile
    int b     = blockIdx.y;   // 0..15 batch
    int split = blockIdx.z;   // 0..1  s half
    int t0 = tile * TM;
    const float* __restrict__ Nmat = g_n + (size_t)b * TT * DD;

    __shared__ __align__(16) float As[BK][TM];   // [k][m], 8 KB
    __shared__ __align__(16) float Bs[BK][TN];   // [k][n], 16 KB
    __shared__ float red[TM][17];                // rowsum reduction, 4.25 KB

    int tid = threadIdx.x;
    int tx = tid & 15;        // column group
    int ty = tid >> 4;        // row group (4 anchors each)
    int am = tid & 63,  ag = tid >> 6;   // A load mapping (ag in 0..3)
    int bm = tid & 127, bg = tid >> 7;   // B load mapping (bg in 0..1)

    float rowsum[4] = {0.f, 0.f, 0.f, 0.f};

#pragma unroll 1
    for (int st = 0; st < 512 / TN; st++) {
        int s0 = split * 512 + st * TN;
        float acc[4][8];
#pragma unroll
        for (int i = 0; i < 4; i++)
#pragma unroll
            for (int j = 0; j < 8; j++) acc[i][j] = 0.f;

#pragma unroll 1
        for (int kk = 0; kk < DD; kk += BK) {
            // Load A chunk: 64 rows x 32 k.  STS bank = am%32 -> conflict-free.
#pragma unroll
            for (int r = 0; r < 2; r++) {
                int rr = ag + r * 4;  // float4 index along k
                float4 v = *reinterpret_cast<const float4*>(
                    Nmat + (size_t)(t0 + am) * DD + kk + rr * 4);
                As[rr * 4 + 0][am] = v.x;
                As[rr * 4 + 1][am] = v.y;
                As[rr * 4 + 2][am] = v.z;
                As[rr * 4 + 3][am] = v.w;
            }
            // Load B chunk: 128 rows x 32 k.
#pragma unroll
            for (int r = 0; r < 4; r++) {
                int rr = bg + r * 2;
                float4 v = *reinterpret_cast<const float4*>(
                    Nmat + (size_t)(s0 + bm) * DD + kk + rr * 4);
                Bs[rr * 4 + 0][bm] = v.x;
                Bs[rr * 4 + 1][bm] = v.y;
                Bs[rr * 4 + 2][bm] = v.z;
                Bs[rr * 4 + 3][bm] = v.w;
            }
            __syncthreads();

#pragma unroll
            for (int k = 0; k < BK; k++) {
                float4 a4  = *reinterpret_cast<const float4*>(&As[k][ty * 4]);
                float4 b4a = *reinterpret_cast<const float4*>(&Bs[k][tx * 4]);
                float4 b4b = *reinterpret_cast<const float4*>(&Bs[k][64 + tx * 4]);
                float a[4]  = {a4.x, a4.y, a4.z, a4.w};
                float bb[8] = {b4a.x, b4a.y, b4a.z, b4a.w,
                               b4b.x, b4b.y, b4b.z, b4b.w};
#pragma unroll
                for (int i = 0; i < 4; i++)
#pragma unroll
                    for (int j = 0; j < 8; j++)
                        acc[i][j] += a[i] * bb[j];
            }
            __syncthreads();
        }

        // Epilogue: scale, mask |s-t|<=1, accumulate exp(sim - M), catch pos.
#pragma unroll
        for (int i = 0; i < 4; i++) {
            int t = t0 + ty * 4 + i;
#pragma unroll
            for (int j = 0; j < 8; j++) {
                int scol = tx * 4 + (j & 3) + ((j >> 2) << 6);  // interleaved cols
                int s = s0 + scol;
                float sim = acc[i][(j & 3) + ((j >> 2) << 2)] * INV_T;
                // acc[i][j] j order matches bb order: j<4 -> cols tx*4+j,
                // j>=4 -> cols 64+tx*4+(j-4); index acc directly with j:
                (void)scol;
                s = s0 + tx * 4 + (j & 3) + ((j >> 2) << 6);
                sim = acc[i][j] * INV_T;
                int dd = s - t;
                if (dd == 1) g_pos[b * TT + t] = sim;
                if (dd < -1 || dd > 1) rowsum[i] += __expf(sim - INV_T);
            }
        }
    }

    // Reduce rowsum across the 16 tx lanes that share each anchor.
#pragma unroll
    for (int i = 0; i < 4; i++) red[ty * 4 + i][tx] = rowsum[i];
    __syncthreads();
    if (tid < TM) {
        float s = 0.f;
#pragma unroll
        for (int x = 0; x < 16; x++) s += red[tid][x];
        g_S[split][b * TT + t0 + tid] = s;
    }
}

// ---------------------------------------------------------------------------
// Kernel 3: combine splits, per-anchor loss, deterministic block reduction.
// ---------------------------------------------------------------------------
__global__ __launch_bounds__(512) void finalize_kernel(float* __restrict__ out) {
    const float M = 1.0f / 0.07f;
    int tid = threadIdx.x;
    float acc = 0.f;
    for (int idx = tid; idx < BB * TT; idx += 512) {
        int t = idx & (TT - 1);
        if (t == 0 || t == TT - 1) continue;   // anchors are t in [1, T-2]
        float S   = g_S[0][idx] + g_S[1][idx];
        float pos = g_pos[idx];
        // loss = logaddexp(pos, M + log(S)) - pos
        acc += logf(expf(pos - M) + S) + M - pos;
    }
    __shared__ float sm[512];
    sm[tid] = acc;
    __syncthreads();
    for (int o = 256; o; o >>= 1) {
        if (tid < o) sm[tid] += sm[tid + o];
        __syncthreads();
    }
    if (tid == 0) out[0] = sm[0] / (float)(BB * (TT - 2));
}

// ---------------------------------------------------------------------------
extern "C" void kernel_launch(void* const* d_in, const int* in_sizes, int n_in,
                              void* d_out, int out_size) {
    const float* features = (const float*)d_in[0];
    float* out = (float*)d_out;

    norm_kernel<<<BB * TT, 128>>>(features);

    dim3 grid(TT / TM, BB, NSPLIT);   // (16, 16, 2) = 512 blocks
    sim_kernel<<<grid, NTHREADS>>>();

    finalize_kernel<<<1, 512>>>(out);
}

// round 5
// speedup vs baseline: 6.6305x; 6.6305x over previous
#include <cuda_runtime.h>
#include <cuda_bf16.h>
#include <cstdint>

#define BB 16
#define TT 1024
#define DD 512

// ---------------- device scratch (no allocation allowed) -------------------
__device__ __align__(16) __nv_bfloat16 g_bf[BB * TT * DD];   // 16 MB normalized bf16
__device__ float g_S16[16][BB * TT];                         // partial neg-sums (s_tile*4 + warp_n)
__device__ float g_pos[BB * TT];                             // sim[t, t+1]

// ---------------- PTX helpers ----------------------------------------------
__device__ __forceinline__ uint32_t smem_u32(const void* p) {
    uint32_t a;
    asm("{ .reg .u64 t; cvta.to.shared.u64 t, %1; cvt.u32.u64 %0, t; }"
        : "=r"(a) : "l"(p));
    return a;
}
__device__ __forceinline__ void cp16(uint32_t dst, const void* src) {
    asm volatile("cp.async.cg.shared.global [%0], [%1], 16;"
                 :: "r"(dst), "l"(src) : "memory");
}
__device__ __forceinline__ void ldsm4(uint32_t r[4], uint32_t addr) {
    asm volatile("ldmatrix.sync.aligned.m8n8.x4.shared.b16 {%0,%1,%2,%3}, [%4];"
                 : "=r"(r[0]), "=r"(r[1]), "=r"(r[2]), "=r"(r[3]) : "r"(addr));
}
__device__ __forceinline__ void mma_bf16(float c[4], uint32_t a0, uint32_t a1,
                                         uint32_t a2, uint32_t a3,
                                         uint32_t b0, uint32_t b1) {
    asm volatile(
        "mma.sync.aligned.m16n8k16.row.col.f32.bf16.bf16.f32 "
        "{%0,%1,%2,%3}, {%4,%5,%6,%7}, {%8,%9}, {%0,%1,%2,%3};"
        : "+f"(c[0]), "+f"(c[1]), "+f"(c[2]), "+f"(c[3])
        : "r"(a0), "r"(a1), "r"(a2), "r"(a3), "r"(b0), "r"(b1));
}

#define STAGE_BYTES 24576           // A: 128*64B + B: 256*64B
#define NCHUNK (DD / 32)            // 16

// ---------------------------------------------------------------------------
// Kernel 1: normalize, emit bf16. One warp per row.
// ---------------------------------------------------------------------------
__global__ __launch_bounds__(256) void norm_kernel(const float* __restrict__ f) {
    int warp = threadIdx.x >> 5, lane = threadIdx.x & 31;
    int row = blockIdx.x * 8 + warp;
    const float4* src = reinterpret_cast<const float4*>(f + (size_t)row * DD);
    float4 v[4];
    float ss = 0.f;
#pragma unroll
    for (int q = 0; q < 4; q++) {
        v[q] = src[lane + q * 32];
        ss += v[q].x * v[q].x + v[q].y * v[q].y + v[q].z * v[q].z + v[q].w * v[q].w;
    }
#pragma unroll
    for (int o = 16; o; o >>= 1) ss += __shfl_xor_sync(0xffffffffu, ss, o);
    float inv = 1.0f / fmaxf(sqrtf(ss), 1e-8f);
#pragma unroll
    for (int q = 0; q < 4; q++) {
        float n[4] = {v[q].x * inv, v[q].y * inv, v[q].z * inv, v[q].w * inv};
        union { __nv_bfloat16 h[4]; uint2 u; } p;
#pragma unroll
        for (int k = 0; k < 4; k++) p.h[k] = __float2bfloat16(n[k]);
        *reinterpret_cast<uint2*>(&g_bf[(size_t)row * DD + (lane + q * 32) * 4]) = p.u;
    }
}

// ---------------------------------------------------------------------------
// Kernel 2: bf16 HMMA Gram + fused masked exp-sum epilogue.
// CTA: 128(t) x 256(s), K=512 in 16 chunks of 32, cp.async double buffer.
// 8 warps as 2(M) x 4(N), warp tile 64x64 (4 m16-tiles x 8 n8-tiles).
// smem row = 64B (32 bf16); 16B slots XOR-swizzled: g' = g ^ (row&3).
// ---------------------------------------------------------------------------
__global__ __launch_bounds__(256, 1) void gram_kernel() {
    __shared__ __align__(1024) char smem[2 * STAGE_BYTES];
    const uint32_t sbase = smem_u32(smem);
    const int tid = threadIdx.x;
    const int wid = tid >> 5, lane = tid & 31;
    const int warp_m = wid >> 2, warp_n = wid & 3;

    const int t0 = blockIdx.x * 128;
    const int b  = blockIdx.y;
    const int s0 = blockIdx.z * 256;
    const __nv_bfloat16* __restrict__ G = g_bf + (size_t)b * TT * DD;

    // ---- load-side per-thread slots (16B each) ----
    const char* asrc[2]; uint32_t adst[2];
#pragma unroll
    for (int i = 0; i < 2; i++) {
        int slot = tid + i * 256, row = slot >> 2, g = slot & 3;
        asrc[i] = reinterpret_cast<const char*>(G + (size_t)(t0 + row) * DD) + g * 16;
        adst[i] = row * 64 + ((g ^ (row & 3)) * 16);
    }
    const char* bsrc[4]; uint32_t bdst[4];
#pragma unroll
    for (int i = 0; i < 4; i++) {
        int slot = tid + i * 256, row = slot >> 2, g = slot & 3;
        bsrc[i] = reinterpret_cast<const char*>(G + (size_t)(s0 + row) * DD) + g * 16;
        bdst[i] = 8192 + row * 64 + ((g ^ (row & 3)) * 16);
    }

    // ---- ldmatrix per-lane offsets ----
    const int a_row = warp_m * 64 + (lane & 15);
    const int ha = lane >> 4;
    uint32_t a_off[2];
#pragma unroll
    for (int ks = 0; ks < 2; ks++)
        a_off[ks] = a_row * 64 + (((ks * 2 + ha) ^ (a_row & 3)) * 16);
    const int n_row = warp_n * 64 + (lane & 7) + ((lane >> 4) << 3);
    const int hb = (lane >> 3) & 1;
    uint32_t b_off[2];
#pragma unroll
    for (int ks = 0; ks < 2; ks++)
        b_off[ks] = 8192 + n_row * 64 + (((ks * 2 + hb) ^ (n_row & 3)) * 16);

    float acc[4][8][4];
#pragma unroll
    for (int mi = 0; mi < 4; mi++)
#pragma unroll
        for (int ni = 0; ni < 8; ni++)
#pragma unroll
            for (int r = 0; r < 4; r++) acc[mi][ni][r] = 0.f;

    // ---- prefetch macro ----
#define PREFETCH(c) do {                                                \
        uint32_t st_ = sbase + ((c) & 1) * STAGE_BYTES;                 \
        size_t ko_ = (size_t)(c) * 64;                                  \
        cp16(st_ + adst[0], asrc[0] + ko_);                             \
        cp16(st_ + adst[1], asrc[1] + ko_);                             \
        cp16(st_ + bdst[0], bsrc[0] + ko_);                             \
        cp16(st_ + bdst[1], bsrc[1] + ko_);                             \
        cp16(st_ + bdst[2], bsrc[2] + ko_);                             \
        cp16(st_ + bdst[3], bsrc[3] + ko_);                             \
        asm volatile("cp.async.commit_group;" ::: "memory");            \
    } while (0)

    PREFETCH(0);
    PREFETCH(1);

#pragma unroll 1
    for (int c = 0; c < NCHUNK; ++c) {
        if (c == NCHUNK - 1)
            asm volatile("cp.async.wait_group 0;" ::: "memory");
        else
            asm volatile("cp.async.wait_group 1;" ::: "memory");
        __syncthreads();

        const uint32_t st = sbase + (c & 1) * STAGE_BYTES;
#pragma unroll
        for (int ks = 0; ks < 2; ks++) {
            uint32_t afr[4][4], bfr[4][4];
#pragma unroll
            for (int mi = 0; mi < 4; mi++) ldsm4(afr[mi], st + a_off[ks] + mi * 1024);
#pragma unroll
            for (int pi = 0; pi < 4; pi++) ldsm4(bfr[pi], st + b_off[ks] + pi * 1024);
#pragma unroll
            for (int mi = 0; mi < 4; mi++)
#pragma unroll
                for (int ni = 0; ni < 8; ni++)
                    mma_bf16(acc[mi][ni],
                             afr[mi][0], afr[mi][1], afr[mi][2], afr[mi][3],
                             bfr[ni >> 1][(ni & 1) * 2], bfr[ni >> 1][(ni & 1) * 2 + 1]);
        }
        __syncthreads();
        if (c + 2 < NCHUNK) PREFETCH(c + 2);
    }

    // ---- epilogue: exp((cos-1)/T) with mask |s-t|<=1, per-row sums ----
    const int rL = lane >> 2, cL = (lane & 3) * 2;
    const int row_base = t0 + warp_m * 64;
    const int col_base = s0 + warp_n * 64;
    float rsum[4][2];
#pragma unroll
    for (int mi = 0; mi < 4; mi++) { rsum[mi][0] = 0.f; rsum[mi][1] = 0.f; }

#pragma unroll
    for (int mi = 0; mi < 4; mi++)
#pragma unroll
        for (int ni = 0; ni < 8; ni++)
#pragma unroll
            for (int r = 0; r < 4; r++) {
                int t = row_base + mi * 16 + rL + (r >> 1) * 8;
                int s = col_base + ni * 8 + cL + (r & 1);
                float v = acc[mi][ni][r];
                int dd = s - t;
                if (dd == 1) g_pos[b * TT + t] = v * 14.2857143f;
                float z = fmaf(v, 20.6099291f, -20.6099291f);  // (cos-1)*log2e/T
                float e;
                asm("ex2.approx.ftz.f32 %0, %1;" : "=f"(e) : "f"(z));
                if ((unsigned)(dd + 1) > 2u) rsum[mi][r >> 1] += e;
            }

    // reduce across the 4 lanes sharing each row, write unique partial slot
    const int slot = blockIdx.z * 4 + warp_n;
#pragma unroll
    for (int mi = 0; mi < 4; mi++)
#pragma unroll
        for (int h = 0; h < 2; h++) {
            float x = rsum[mi][h];
            x += __shfl_xor_sync(0xffffffffu, x, 1);
            x += __shfl_xor_sync(0xffffffffu, x, 2);
            if ((lane & 3) == 0)
                g_S16[slot][b * TT + row_base + mi * 16 + rL + h * 8] = x;
        }
}

// ---------------------------------------------------------------------------
// Kernel 3: combine 16 partials, per-anchor loss, deterministic reduction.
// ---------------------------------------------------------------------------
__global__ __launch_bounds__(1024) void finalize_kernel(float* __restrict__ out) {
    const float M = 14.285714285714286f;   // 1/0.07
    int tid = threadIdx.x;
    float acc = 0.f;
    for (int idx = tid; idx < BB * TT; idx += 1024) {
        int tt = idx & (TT - 1);
        if (tt == 0 || tt == TT - 1) continue;
        float S = 0.f;
#pragma unroll
        for (int p = 0; p < 16; p++) S += g_S16[p][idx];
        float pos = g_pos[idx];
        acc += logf(expf(pos - M) + S) + M - pos;
    }
    __shared__ float sm[1024];
    sm[tid] = acc;
    __syncthreads();
    for (int o = 512; o; o >>= 1) {
        if (tid < o) sm[tid] += sm[tid + o];
        __syncthreads();
    }
    if (tid == 0) out[0] = sm[0] / (float)(BB * (TT - 2));
}

// ---------------------------------------------------------------------------
extern "C" void kernel_launch(void* const* d_in, const int* in_sizes, int n_in,
                              void* d_out, int out_size) {
    const float* features = (const float*)d_in[0];
    float* out = (float*)d_out;

    norm_kernel<<<BB * TT / 8, 256>>>(features);
    gram_kernel<<<dim3(TT / 128, BB, TT / 256), 256>>>();
    finalize_kernel<<<1, 1024>>>(out);
}

// round 7
// speedup vs baseline: 7.5718x; 1.1420x over previous
#include <cuda_runtime.h>
#include <cuda_bf16.h>
#include <cstdint>

#define BB 16
#define TT 1024
#define DD 512

// ---------------- device scratch (no allocation allowed) -------------------
__device__ __align__(16) __nv_bfloat16 g_bf[BB * TT * DD];   // 16 MB normalized bf16
__device__ float g_S16[16][BB * TT];                         // partial neg-sums
__device__ float g_pos[BB * TT];                             // sim[t, t+1]

// ---------------- PTX helpers ----------------------------------------------
__device__ __forceinline__ uint32_t smem_u32(const void* p) {
    uint32_t a;
    asm("{ .reg .u64 t; cvta.to.shared.u64 t, %1; cvt.u32.u64 %0, t; }"
        : "=r"(a) : "l"(p));
    return a;
}
__device__ __forceinline__ void cp16(uint32_t dst, const void* src) {
    asm volatile("cp.async.cg.shared.global [%0], [%1], 16;"
                 :: "r"(dst), "l"(src) : "memory");
}
__device__ __forceinline__ void ldsm4(uint32_t r[4], uint32_t addr) {
    asm volatile("ldmatrix.sync.aligned.m8n8.x4.shared.b16 {%0,%1,%2,%3}, [%4];"
                 : "=r"(r[0]), "=r"(r[1]), "=r"(r[2]), "=r"(r[3]) : "r"(addr));
}
__device__ __forceinline__ void mma_bf16(float c[4], uint32_t a0, uint32_t a1,
                                         uint32_t a2, uint32_t a3,
                                         uint32_t b0, uint32_t b1) {
    asm volatile(
        "mma.sync.aligned.m16n8k16.row.col.f32.bf16.bf16.f32 "
        "{%0,%1,%2,%3}, {%4,%5,%6,%7}, {%8,%9}, {%0,%1,%2,%3};"
        : "+f"(c[0]), "+f"(c[1]), "+f"(c[2]), "+f"(c[3])
        : "r"(a0), "r"(a1), "r"(a2), "r"(a3), "r"(b0), "r"(b1));
}

#define STAGE_BYTES 24576           // A: 128*64B + B: 256*64B
#define NSTAGE 4
#define NCHUNK (DD / 32)            // 16
// conflict-free swizzle: quad(row) = ((row&1)<<2) | (g ^ ((row>>1)&3))
// -> each 8-row ldmatrix phase covers all 8 bank quads exactly once.
#define SWZ(g, row) (((g) ^ (((row) >> 1) & 3)) * 16)

// ---------------------------------------------------------------------------
// Kernel 1: normalize, emit bf16. One warp per row.
// ---------------------------------------------------------------------------
__global__ __launch_bounds__(256) void norm_kernel(const float* __restrict__ f) {
    int warp = threadIdx.x >> 5, lane = threadIdx.x & 31;
    int row = blockIdx.x * 8 + warp;
    const float4* src = reinterpret_cast<const float4*>(f + (size_t)row * DD);
    float4 v[4];
    float ss = 0.f;
#pragma unroll
    for (int q = 0; q < 4; q++) {
        v[q] = src[lane + q * 32];
        ss += v[q].x * v[q].x + v[q].y * v[q].y + v[q].z * v[q].z + v[q].w * v[q].w;
    }
#pragma unroll
    for (int o = 16; o; o >>= 1) ss += __shfl_xor_sync(0xffffffffu, ss, o);
    float inv = 1.0f / fmaxf(sqrtf(ss), 1e-8f);
#pragma unroll
    for (int q = 0; q < 4; q++) {
        float n[4] = {v[q].x * inv, v[q].y * inv, v[q].z * inv, v[q].w * inv};
        union { __nv_bfloat16 h[4]; uint2 u; } p;
#pragma unroll
        for (int k = 0; k < 4; k++) p.h[k] = __float2bfloat16(n[k]);
        *reinterpret_cast<uint2*>(&g_bf[(size_t)row * DD + (lane + q * 32) * 4]) = p.u;
    }
}

// ---------------------------------------------------------------------------
// Kernel 2: bf16 HMMA Gram + fused masked exp-sum epilogue.
// CTA: 128(t) x 256(s), K=512 in 16 chunks of 32, 4-stage cp.async pipeline.
// 8 warps as 2(M) x 4(N), warp tile 64x64.
// ---------------------------------------------------------------------------
__global__ __launch_bounds__(256, 1) void gram_kernel() {
    extern __shared__ __align__(1024) char smem[];
    const uint32_t sbase = smem_u32(smem);
    const int tid = threadIdx.x;
    const int wid = tid >> 5, lane = tid & 31;
    const int warp_m = wid >> 2, warp_n = wid & 3;

    const int t0 = blockIdx.x * 128;
    const int b  = blockIdx.y;
    const int s0 = blockIdx.z * 256;
    const __nv_bfloat16* __restrict__ G = g_bf + (size_t)b * TT * DD;

    // ---- load-side per-thread slots (16B each) ----
    const char* asrc[2]; uint32_t adst[2];
#pragma unroll
    for (int i = 0; i < 2; i++) {
        int slot = tid + i * 256, row = slot >> 2, g = slot & 3;
        asrc[i] = reinterpret_cast<const char*>(G + (size_t)(t0 + row) * DD) + g * 16;
        adst[i] = row * 64 + SWZ(g, row);
    }
    const char* bsrc[4]; uint32_t bdst[4];
#pragma unroll
    for (int i = 0; i < 4; i++) {
        int slot = tid + i * 256, row = slot >> 2, g = slot & 3;
        bsrc[i] = reinterpret_cast<const char*>(G + (size_t)(s0 + row) * DD) + g * 16;
        bdst[i] = 8192 + row * 64 + SWZ(g, row);
    }

    // ---- ldmatrix per-lane offsets ----
    const int a_row = warp_m * 64 + (lane & 15);
    const int ha = lane >> 4;
    uint32_t a_off[2];
#pragma unroll
    for (int ks = 0; ks < 2; ks++)
        a_off[ks] = a_row * 64 + SWZ(ks * 2 + ha, a_row);
    const int n_row = warp_n * 64 + (lane & 7) + ((lane >> 4) << 3);
    const int hb = (lane >> 3) & 1;
    uint32_t b_off[2];
#pragma unroll
    for (int ks = 0; ks < 2; ks++)
        b_off[ks] = 8192 + n_row * 64 + SWZ(ks * 2 + hb, n_row);

    float acc[4][8][4];
#pragma unroll
    for (int mi = 0; mi < 4; mi++)
#pragma unroll
        for (int ni = 0; ni < 8; ni++)
#pragma unroll
            for (int r = 0; r < 4; r++) acc[mi][ni][r] = 0.f;

#define PREFETCH(c) do {                                                \
        uint32_t st_ = sbase + ((c) & (NSTAGE - 1)) * STAGE_BYTES;      \
        size_t ko_ = (size_t)(c) * 64;                                  \
        cp16(st_ + adst[0], asrc[0] + ko_);                             \
        cp16(st_ + adst[1], asrc[1] + ko_);                             \
        cp16(st_ + bdst[0], bsrc[0] + ko_);                             \
        cp16(st_ + bdst[1], bsrc[1] + ko_);                             \
        cp16(st_ + bdst[2], bsrc[2] + ko_);                             \
        cp16(st_ + bdst[3], bsrc[3] + ko_);                             \
        asm volatile("cp.async.commit_group;" ::: "memory");            \
    } while (0)

    PREFETCH(0);
    PREFETCH(1);
    PREFETCH(2);

#pragma unroll 1
    for (int c = 0; c < NCHUNK; ++c) {
        if (c + 3 <= NCHUNK)
            asm volatile("cp.async.wait_group 2;" ::: "memory");
        else if (c + 2 == NCHUNK)
            asm volatile("cp.async.wait_group 1;" ::: "memory");
        else
            asm volatile("cp.async.wait_group 0;" ::: "memory");
        __syncthreads();

        if (c + 3 < NCHUNK) PREFETCH(c + 3);

        const uint32_t st = sbase + (c & (NSTAGE - 1)) * STAGE_BYTES;
        uint32_t afr[2][4][4], bfr[2][4][4];
#pragma unroll
        for (int ks = 0; ks < 2; ks++) {
#pragma unroll
            for (int mi = 0; mi < 4; mi++) ldsm4(afr[ks][mi], st + a_off[ks] + mi * 1024);
#pragma unroll
            for (int pi = 0; pi < 4; pi++) ldsm4(bfr[ks][pi], st + b_off[ks] + pi * 1024);
        }
#pragma unroll
        for (int ks = 0; ks < 2; ks++)
#pragma unroll
            for (int mi = 0; mi < 4; mi++)
#pragma unroll
                for (int ni = 0; ni < 8; ni++)
                    mma_bf16(acc[mi][ni],
                             afr[ks][mi][0], afr[ks][mi][1],
                             afr[ks][mi][2], afr[ks][mi][3],
                             bfr[ks][ni >> 1][(ni & 1) * 2],
                             bfr[ks][ni >> 1][(ni & 1) * 2 + 1]);
    }

    // ---- epilogue: exp((cos-1)/T) with mask |s-t|<=1, per-row sums ----
    const int rL = lane >> 2, cL = (lane & 3) * 2;
    const int row_base = t0 + warp_m * 64;
    const int col_base = s0 + warp_n * 64;
    const int posbase = b * TT;
    float rsum[4][2];
#pragma unroll
    for (int mi = 0; mi < 4; mi++) { rsum[mi][0] = 0.f; rsum[mi][1] = 0.f; }

#pragma unroll
    for (int mi = 0; mi < 4; mi++)
#pragma unroll
        for (int ni = 0; ni < 8; ni++)
#pragma unroll
            for (int r = 0; r < 4; r++) {
                int t = row_base + mi * 16 + rL + (r >> 1) * 8;
                int s = col_base + ni * 8 + cL + (r & 1);
                float v = acc[mi][ni][r];
                int dd = s - t;
                if (dd == 1) g_pos[posbase + t] = v * 14.2857143f;
                float z = fmaf(v, 20.6099291f, -20.6099291f);  // (cos-1)*log2e/T
                float e;
                asm("ex2.approx.ftz.f32 %0, %1;" : "=f"(e) : "f"(z));
                if ((unsigned)(dd + 1) > 2u) rsum[mi][r >> 1] += e;
            }

    const int slot = blockIdx.z * 4 + warp_n;
#pragma unroll
    for (int mi = 0; mi < 4; mi++)
#pragma unroll
        for (int h = 0; h < 2; h++) {
            float x = rsum[mi][h];
            x += __shfl_xor_sync(0xffffffffu, x, 1);
            x += __shfl_xor_sync(0xffffffffu, x, 2);
            if ((lane & 3) == 0)
                g_S16[slot][posbase + row_base + mi * 16 + rL + h * 8] = x;
        }
}

// ---------------------------------------------------------------------------
// Kernel 3: combine 16 partials, per-anchor loss, deterministic reduction.
// ---------------------------------------------------------------------------
__global__ __launch_bounds__(1024) void finalize_kernel(float* __restrict__ out) {
    const float M = 14.285714285714286f;   // 1/0.07
    int tid = threadIdx.x;
    float acc = 0.f;
    for (int idx = tid; idx < BB * TT; idx += 1024) {
        int tt = idx & (TT - 1);
        if (tt == 0 || tt == TT - 1) continue;
        float S = 0.f;
#pragma unroll
        for (int p = 0; p < 16; p++) S += g_S16[p][idx];
        float pos = g_pos[idx];
        acc += logf(expf(pos - M) + S) + M - pos;
    }
    __shared__ float sm[1024];
    sm[tid] = acc;
    __syncthreads();
    for (int o = 512; o; o >>= 1) {
        if (tid < o) sm[tid] += sm[tid + o];
        __syncthreads();
    }
    if (tid == 0) out[0] = sm[0] / (float)(BB * (TT - 2));
}

// ---------------------------------------------------------------------------
extern "C" void kernel_launch(void* const* d_in, const int* in_sizes, int n_in,
                              void* d_out, int out_size) {
    const float* features = (const float*)d_in[0];
    float* out = (float*)d_out;

    cudaFuncSetAttribute(gram_kernel,
                         cudaFuncAttributeMaxDynamicSharedMemorySize,
                         NSTAGE * STAGE_BYTES);

    norm_kernel<<<BB * TT / 8, 256>>>(features);
    gram_kernel<<<dim3(TT / 128, BB, TT / 256), 256, NSTAGE * STAGE_BYTES>>>();
    finalize_kernel<<<1, 1024>>>(out);
}

// round 10
// speedup vs baseline: 8.5153x; 1.1246x over previous
#include <cuda_runtime.h>
#include <cuda_bf16.h>
#include <cstdint>

#define BB 16
#define TT 1024
#define DD 512

// ---------------- device scratch (no allocation allowed) -------------------
__device__ __align__(16) __nv_bfloat16 g_bf[BB * TT * DD];   // 16 MB normalized bf16
__device__ float g_S32[32][BB * TT];   // 0..15 row-slots (j*4+warp_n), 16..31 col-slots (16+i*2+warp_m)
__device__ float g_pos[BB * TT];       // sim[t, t+1]

// Symmetric tile schedule: 20 tiles/batch. code = i | (j<<4) | (full<<8)
__constant__ int c_tiles[20] = {
    0x000, 0x001,                               // j=0 diag
    0x110, 0x111, 0x012, 0x013,                 // j=1: full(0,1),(1,1) diag(2,1),(3,1)
    0x120, 0x121, 0x122, 0x123, 0x024, 0x025,   // j=2: full i=0..3, diag i=4,5
    0x130, 0x131, 0x132, 0x133, 0x134, 0x135, 0x036, 0x037  // j=3
};

// ---------------- PTX helpers ----------------------------------------------
__device__ __forceinline__ uint32_t smem_u32(const void* p) {
    uint32_t a;
    asm("{ .reg .u64 t; cvta.to.shared.u64 t, %1; cvt.u32.u64 %0, t; }"
        : "=r"(a) : "l"(p));
    return a;
}
__device__ __forceinline__ void cp16(uint32_t dst, const void* src) {
    asm volatile("cp.async.cg.shared.global [%0], [%1], 16;"
                 :: "r"(dst), "l"(src) : "memory");
}
__device__ __forceinline__ void ldsm4(uint32_t r[4], uint32_t addr) {
    asm volatile("ldmatrix.sync.aligned.m8n8.x4.shared.b16 {%0,%1,%2,%3}, [%4];"
                 : "=r"(r[0]), "=r"(r[1]), "=r"(r[2]), "=r"(r[3]) : "r"(addr));
}
__device__ __forceinline__ void mma_bf16(float c[4], uint32_t a0, uint32_t a1,
                                         uint32_t a2, uint32_t a3,
                                         uint32_t b0, uint32_t b1) {
    asm volatile(
        "mma.sync.aligned.m16n8k16.row.col.f32.bf16.bf16.f32 "
        "{%0,%1,%2,%3}, {%4,%5,%6,%7}, {%8,%9}, {%0,%1,%2,%3};"
        : "+f"(c[0]), "+f"(c[1]), "+f"(c[2]), "+f"(c[3])
        : "r"(a0), "r"(a1), "r"(a2), "r"(a3), "r"(b0), "r"(b1));
}

#define STAGE_BYTES 24576           // A: 128*64B + B: 256*64B
#define NSTAGE 4
#define NCHUNK (DD / 32)            // 16
// conflict-free swizzle: quad(row) = ((row&1)<<2) | (g ^ ((row>>1)&3))
#define SWZ(g, row) (((g) ^ (((row) >> 1) & 3)) * 16)

// ---------------------------------------------------------------------------
// Kernel 1: normalize, emit bf16. One warp per row.
// ---------------------------------------------------------------------------
__global__ __launch_bounds__(256) void norm_kernel(const float* __restrict__ f) {
    int warp = threadIdx.x >> 5, lane = threadIdx.x & 31;
    int row = blockIdx.x * 8 + warp;
    const float4* src = reinterpret_cast<const float4*>(f + (size_t)row * DD);
    float4 v[4];
    float ss = 0.f;
#pragma unroll
    for (int q = 0; q < 4; q++) {
        v[q] = src[lane + q * 32];
        ss += v[q].x * v[q].x + v[q].y * v[q].y + v[q].z * v[q].z + v[q].w * v[q].w;
    }
#pragma unroll
    for (int o = 16; o; o >>= 1) ss += __shfl_xor_sync(0xffffffffu, ss, o);
    float inv = 1.0f / fmaxf(sqrtf(ss), 1e-8f);
#pragma unroll
    for (int q = 0; q < 4; q++) {
        float n[4] = {v[q].x * inv, v[q].y * inv, v[q].z * inv, v[q].w * inv};
        union { __nv_bfloat16 h[4]; uint2 u; } p;
#pragma unroll
        for (int k = 0; k < 4; k++) p.h[k] = __float2bfloat16(n[k]);
        *reinterpret_cast<uint2*>(&g_bf[(size_t)row * DD + (lane + q * 32) * 4]) = p.u;
    }
}

// ---------------------------------------------------------------------------
// Kernel 2: bf16 HMMA Gram on symmetric tile schedule + fused exp epilogue.
// Tile: 128(t) x 256(s); full (above-diag) tiles also mirror into col sums.
// ---------------------------------------------------------------------------
__global__ __launch_bounds__(256, 1) void gram_kernel() {
    extern __shared__ __align__(1024) char smem[];
    const uint32_t sbase = smem_u32(smem);
    const int tid = threadIdx.x;
    const int wid = tid >> 5, lane = tid & 31;
    const int warp_m = wid >> 2, warp_n = wid & 3;

    const int code = c_tiles[blockIdx.x];
    const int ti = code & 15;            // row block (128)
    const int tj = (code >> 4) & 15;     // col block (256)
    const int is_full = code >> 8;       // 1 = strictly above diagonal
    const int t0 = ti * 128;
    const int s0 = tj * 256;
    const int b  = blockIdx.y;
    const __nv_bfloat16* __restrict__ G = g_bf + (size_t)b * TT * DD;

    // ---- load-side per-thread slots (16B each) ----
    const char* asrc[2]; uint32_t adst[2];
#pragma unroll
    for (int i = 0; i < 2; i++) {
        int slot = tid + i * 256, row = slot >> 2, g = slot & 3;
        asrc[i] = reinterpret_cast<const char*>(G + (size_t)(t0 + row) * DD) + g * 16;
        adst[i] = row * 64 + SWZ(g, row);
    }
    const char* bsrc[4]; uint32_t bdst[4];
#pragma unroll
    for (int i = 0; i < 4; i++) {
        int slot = tid + i * 256, row = slot >> 2, g = slot & 3;
        bsrc[i] = reinterpret_cast<const char*>(G + (size_t)(s0 + row) * DD) + g * 16;
        bdst[i] = 8192 + row * 64 + SWZ(g, row);
    }

    // ---- ldmatrix per-lane offsets ----
    const int a_row = warp_m * 64 + (lane & 15);
    const int ha = lane >> 4;
    uint32_t a_off[2];
#pragma unroll
    for (int ks = 0; ks < 2; ks++)
        a_off[ks] = a_row * 64 + SWZ(ks * 2 + ha, a_row);
    const int n_row = warp_n * 64 + (lane & 7) + ((lane >> 4) << 3);
    const int hb = (lane >> 3) & 1;
    uint32_t b_off[2];
#pragma unroll
    for (int ks = 0; ks < 2; ks++)
        b_off[ks] = 8192 + n_row * 64 + SWZ(ks * 2 + hb, n_row);

    float acc[4][8][4];
#pragma unroll
    for (int mi = 0; mi < 4; mi++)
#pragma unroll
        for (int ni = 0; ni < 8; ni++)
#pragma unroll
            for (int r = 0; r < 4; r++) acc[mi][ni][r] = 0.f;

#define PREFETCH(c) do {                                                \
        uint32_t st_ = sbase + ((c) & (NSTAGE - 1)) * STAGE_BYTES;      \
        size_t ko_ = (size_t)(c) * 64;                                  \
        cp16(st_ + adst[0], asrc[0] + ko_);                             \
        cp16(st_ + adst[1], asrc[1] + ko_);                             \
        cp16(st_ + bdst[0], bsrc[0] + ko_);                             \
        cp16(st_ + bdst[1], bsrc[1] + ko_);                             \
        cp16(st_ + bdst[2], bsrc[2] + ko_);                             \
        cp16(st_ + bdst[3], bsrc[3] + ko_);                             \
        asm volatile("cp.async.commit_group;" ::: "memory");            \
    } while (0)

    PREFETCH(0);
    PREFETCH(1);
    PREFETCH(2);

#pragma unroll 1
    for (int c = 0; c < NCHUNK; ++c) {
        if (c + 3 <= NCHUNK)
            asm volatile("cp.async.wait_group 2;" ::: "memory");
        else if (c + 2 == NCHUNK)
            asm volatile("cp.async.wait_group 1;" ::: "memory");
        else
            asm volatile("cp.async.wait_group 0;" ::: "memory");
        __syncthreads();

        if (c + 3 < NCHUNK) PREFETCH(c + 3);

        const uint32_t st = sbase + (c & (NSTAGE - 1)) * STAGE_BYTES;
        uint32_t afr[2][4][4], bfr[2][4][4];
#pragma unroll
        for (int ks = 0; ks < 2; ks++) {
#pragma unroll
            for (int mi = 0; mi < 4; mi++) ldsm4(afr[ks][mi], st + a_off[ks] + mi * 1024);
#pragma unroll
            for (int pi = 0; pi < 4; pi++) ldsm4(bfr[ks][pi], st + b_off[ks] + pi * 1024);
        }
#pragma unroll
        for (int ks = 0; ks < 2; ks++)
#pragma unroll
            for (int mi = 0; mi < 4; mi++)
#pragma unroll
                for (int ni = 0; ni < 8; ni++)
                    mma_bf16(acc[mi][ni],
                             afr[ks][mi][0], afr[ks][mi][1],
                             afr[ks][mi][2], afr[ks][mi][3],
                             bfr[ks][ni >> 1][(ni & 1) * 2],
                             bfr[ks][ni >> 1][(ni & 1) * 2 + 1]);
    }

    // ---- epilogue: exp((cos-1)/T), mask |s-t|<=1; row sums (+ col sums) ----
    const int rL = lane >> 2, cL = (lane & 3) * 2;
    const int row_base = t0 + warp_m * 64;
    const int col_base = s0 + warp_n * 64;
    const int posbase = b * TT;
    float rsum[4][2];
    float csum[8][2];
#pragma unroll
    for (int mi = 0; mi < 4; mi++) { rsum[mi][0] = 0.f; rsum[mi][1] = 0.f; }
#pragma unroll
    for (int ni = 0; ni < 8; ni++) { csum[ni][0] = 0.f; csum[ni][1] = 0.f; }

#pragma unroll
    for (int mi = 0; mi < 4; mi++)
#pragma unroll
        for (int ni = 0; ni < 8; ni++)
#pragma unroll
            for (int r = 0; r < 4; r++) {
                int t = row_base + mi * 16 + rL + (r >> 1) * 8;
                int s = col_base + ni * 8 + cL + (r & 1);
                float v = acc[mi][ni][r];
                int dd = s - t;
                if (dd == 1) g_pos[posbase + t] = v * 14.2857143f;
                float z = fmaf(v, 20.6099291f, -20.6099291f);  // (cos-1)*log2e/T
                float e;
                asm("ex2.approx.ftz.f32 %0, %1;" : "=f"(e) : "f"(z));
                bool keep = (unsigned)(dd + 1) > 2u;
                float em = keep ? e : 0.f;
                rsum[mi][r >> 1] += em;
                csum[ni][r & 1]  += em;
            }

    // row sums: reduce over the 4 lanes sharing each row (lane bits 0,1)
    const int rslot = tj * 4 + warp_n;
#pragma unroll
    for (int mi = 0; mi < 4; mi++)
#pragma unroll
        for (int h = 0; h < 2; h++) {
            float x = rsum[mi][h];
            x += __shfl_xor_sync(0xffffffffu, x, 1);
            x += __shfl_xor_sync(0xffffffffu, x, 2);
            if ((lane & 3) == 0)
                g_S32[rslot][posbase + row_base + mi * 16 + rL + h * 8] = x;
        }

    // col sums (mirror), full tiles only: reduce over lane bits 2,3,4 (rows)
    if (is_full) {
        const int cslot = 16 + ti * 2 + warp_m;
#pragma unroll
        for (int ni = 0; ni < 8; ni++)
#pragma unroll
            for (int p = 0; p < 2; p++) {
                float x = csum[ni][p];
                x += __shfl_xor_sync(0xffffffffu, x, 4);
                x += __shfl_xor_sync(0xffffffffu, x, 8);
                x += __shfl_xor_sync(0xffffffffu, x, 16);
                if ((lane & 28) == 0)
                    g_S32[cslot][posbase + col_base + ni * 8 + (lane & 3) * 2 + p] = x;
            }
    }
}

// ---------------------------------------------------------------------------
// Kernel 3: combine 32 partials, per-anchor loss, deterministic reduction.
// ---------------------------------------------------------------------------
__global__ __launch_bounds__(1024) void finalize_kernel(float* __restrict__ out) {
    const float M = 14.285714285714286f;   // 1/0.07
    int tid = threadIdx.x;
    float acc = 0.f;
    for (int idx = tid; idx < BB * TT; idx += 1024) {
        int tt = idx & (TT - 1);
        if (tt == 0 || tt == TT - 1) continue;
        float S = 0.f;
#pragma unroll
        for (int p = 0; p < 32; p++) S += g_S32[p][idx];
        float pos = g_pos[idx];
        acc += logf(expf(pos - M) + S) + M - pos;
    }
    __shared__ float sm[1024];
    sm[tid] = acc;
    __syncthreads();
    for (int o = 512; o; o >>= 1) {
        if (tid < o) sm[tid] += sm[tid + o];
        __syncthreads();
    }
    if (tid == 0) out[0] = sm[0] / (float)(BB * (TT - 2));
}

// ---------------------------------------------------------------------------
extern "C" void kernel_launch(void* const* d_in, const int* in_sizes, int n_in,
                              void* d_out, int out_size) {
    const float* features = (const float*)d_in[0];
    float* out = (float*)d_out;

    cudaFuncSetAttribute(gram_kernel,
                         cudaFuncAttributeMaxDynamicSharedMemorySize,
                         NSTAGE * STAGE_BYTES);

    norm_kernel<<<BB * TT / 8, 256>>>(features);
    gram_kernel<<<dim3(20, BB), 256, NSTAGE * STAGE_BYTES>>>();
    finalize_kernel<<<1, 1024>>>(out);
}

// round 12
// speedup vs baseline: 11.3823x; 1.3367x over previous
#include <cuda_runtime.h>
#include <cuda_bf16.h>
#include <cstdint>

#define BB 16
#define TT 1024
#define DD 512

// ---------------- device scratch (no allocation allowed) -------------------
__device__ __align__(16) __nv_bfloat16 g_bf[BB * TT * DD];   // 16 MB normalized bf16
__device__ float g_S48[48][BB * TT];   // 0..31 row-slots (j*4+wn), 32..47 col-slots (32+i*2+wm)
__device__ float g_pos[BB * TT];       // sim[t, t+1]
__device__ float g_part[64];           // per-block partial losses

// Symmetric 128x128 tile schedule: 36 tiles/batch. code = i | (j<<4) | (full<<8)
__constant__ int c_tiles[36] = {
    0x000, 0x011, 0x022, 0x033, 0x044, 0x055, 0x066, 0x077,   // diagonal
    0x110,
    0x120, 0x121,
    0x130, 0x131, 0x132,
    0x140, 0x141, 0x142, 0x143,
    0x150, 0x151, 0x152, 0x153, 0x154,
    0x160, 0x161, 0x162, 0x163, 0x164, 0x165,
    0x170, 0x171, 0x172, 0x173, 0x174, 0x175, 0x176
};

// ---------------- PTX helpers ----------------------------------------------
__device__ __forceinline__ uint32_t smem_u32(const void* p) {
    uint32_t a;
    asm("{ .reg .u64 t; cvta.to.shared.u64 t, %1; cvt.u32.u64 %0, t; }"
        : "=r"(a) : "l"(p));
    return a;
}
__device__ __forceinline__ void cp16(uint32_t dst, const void* src) {
    asm volatile("cp.async.cg.shared.global [%0], [%1], 16;"
                 :: "r"(dst), "l"(src) : "memory");
}
__device__ __forceinline__ void ldsm4(uint32_t r[4], uint32_t addr) {
    asm volatile("ldmatrix.sync.aligned.m8n8.x4.shared.b16 {%0,%1,%2,%3}, [%4];"
                 : "=r"(r[0]), "=r"(r[1]), "=r"(r[2]), "=r"(r[3]) : "r"(addr));
}
__device__ __forceinline__ void mma_bf16(float c[4], uint32_t a0, uint32_t a1,
                                         uint32_t a2, uint32_t a3,
                                         uint32_t b0, uint32_t b1) {
    asm volatile(
        "mma.sync.aligned.m16n8k16.row.col.f32.bf16.bf16.f32 "
        "{%0,%1,%2,%3}, {%4,%5,%6,%7}, {%8,%9}, {%0,%1,%2,%3};"
        : "+f"(c[0]), "+f"(c[1]), "+f"(c[2]), "+f"(c[3])
        : "r"(a0), "r"(a1), "r"(a2), "r"(a3), "r"(b0), "r"(b1));
}

#define STAGE_BYTES 16384           // A: 128*64B + B: 128*64B
#define NSTAGE 4
#define NCHUNK (DD / 32)            // 16
// conflict-free swizzle: quad(row) = ((row&1)<<2) | (g ^ ((row>>1)&3))
#define SWZ(g, row) (((g) ^ (((row) >> 1) & 3)) * 16)

// ---------------------------------------------------------------------------
// Kernel 1: normalize, emit bf16. Two rows per warp (ILP for latency hiding).
// ---------------------------------------------------------------------------
__global__ __launch_bounds__(256) void norm_kernel(const float* __restrict__ f) {
    int warp = threadIdx.x >> 5, lane = threadIdx.x & 31;
    int row0 = (blockIdx.x * 8 + warp) * 2;
    float4 v[2][4];
    float ss0 = 0.f, ss1 = 0.f;
#pragma unroll
    for (int q = 0; q < 4; q++) {
        v[0][q] = reinterpret_cast<const float4*>(f + (size_t)row0 * DD)[lane + q * 32];
        v[1][q] = reinterpret_cast<const float4*>(f + (size_t)(row0 + 1) * DD)[lane + q * 32];
        ss0 += v[0][q].x * v[0][q].x + v[0][q].y * v[0][q].y
             + v[0][q].z * v[0][q].z + v[0][q].w * v[0][q].w;
        ss1 += v[1][q].x * v[1][q].x + v[1][q].y * v[1][q].y
             + v[1][q].z * v[1][q].z + v[1][q].w * v[1][q].w;
    }
#pragma unroll
    for (int o = 16; o; o >>= 1) {
        ss0 += __shfl_xor_sync(0xffffffffu, ss0, o);
        ss1 += __shfl_xor_sync(0xffffffffu, ss1, o);
    }
    float inv0 = 1.0f / fmaxf(sqrtf(ss0), 1e-8f);
    float inv1 = 1.0f / fmaxf(sqrtf(ss1), 1e-8f);
#pragma unroll
    for (int rr = 0; rr < 2; rr++) {
        float inv = rr ? inv1 : inv0;
#pragma unroll
        for (int q = 0; q < 4; q++) {
            float n[4] = {v[rr][q].x * inv, v[rr][q].y * inv,
                          v[rr][q].z * inv, v[rr][q].w * inv};
            union { __nv_bfloat16 h[4]; uint2 u; } p;
#pragma unroll
            for (int k = 0; k < 4; k++) p.h[k] = __float2bfloat16(n[k]);
            *reinterpret_cast<uint2*>(
                &g_bf[(size_t)(row0 + rr) * DD + (lane + q * 32) * 4]) = p.u;
        }
    }
}

// ---------------------------------------------------------------------------
// Kernel 2: bf16 HMMA Gram, 128x128 symmetric tiles + fused exp epilogue.
// 8 warps as 2(M) x 4(N), warp tile 64x32.
// ---------------------------------------------------------------------------
__global__ __launch_bounds__(256, 1) void gram_kernel() {
    extern __shared__ __align__(1024) char smem[];
    const uint32_t sbase = smem_u32(smem);
    const int tid = threadIdx.x;
    const int wid = tid >> 5, lane = tid & 31;
    const int warp_m = wid >> 2, warp_n = wid & 3;

    const int code = c_tiles[blockIdx.x];
    const int ti = code & 15;            // row block
    const int tj = (code >> 4) & 15;     // col block
    const int is_full = code >> 8;       // 1 = strictly above diagonal
    const int t0 = ti * 128;
    const int s0 = tj * 128;
    const int b  = blockIdx.y;
    const __nv_bfloat16* __restrict__ G = g_bf + (size_t)b * TT * DD;

    // ---- load-side per-thread slots (16B each): 2 A + 2 B ----
    const char* asrc[2]; uint32_t adst[2];
    const char* bsrc[2]; uint32_t bdst[2];
#pragma unroll
    for (int i = 0; i < 2; i++) {
        int slot = tid + i * 256, row = slot >> 2, g = slot & 3;
        asrc[i] = reinterpret_cast<const char*>(G + (size_t)(t0 + row) * DD) + g * 16;
        adst[i] = row * 64 + SWZ(g, row);
        bsrc[i] = reinterpret_cast<const char*>(G + (size_t)(s0 + row) * DD) + g * 16;
        bdst[i] = 8192 + row * 64 + SWZ(g, row);
    }

    // ---- ldmatrix per-lane offsets ----
    const int a_row = warp_m * 64 + (lane & 15);
    const int ha = lane >> 4;
    uint32_t a_off[2];
#pragma unroll
    for (int ks = 0; ks < 2; ks++)
        a_off[ks] = a_row * 64 + SWZ(ks * 2 + ha, a_row);
    const int n_row = warp_n * 32 + (lane & 7) + ((lane >> 4) << 3);
    const int hb = (lane >> 3) & 1;
    uint32_t b_off[2];
#pragma unroll
    for (int ks = 0; ks < 2; ks++)
        b_off[ks] = 8192 + n_row * 64 + SWZ(ks * 2 + hb, n_row);

    float acc[4][4][4];
#pragma unroll
    for (int mi = 0; mi < 4; mi++)
#pragma unroll
        for (int ni = 0; ni < 4; ni++)
#pragma unroll
            for (int r = 0; r < 4; r++) acc[mi][ni][r] = 0.f;

#define PREFETCH(c) do {                                                \
        uint32_t st_ = sbase + ((c) & (NSTAGE - 1)) * STAGE_BYTES;      \
        size_t ko_ = (size_t)(c) * 64;                                  \
        cp16(st_ + adst[0], asrc[0] + ko_);                             \
        cp16(st_ + adst[1], asrc[1] + ko_);                             \
        cp16(st_ + bdst[0], bsrc[0] + ko_);                             \
        cp16(st_ + bdst[1], bsrc[1] + ko_);                             \
        asm volatile("cp.async.commit_group;" ::: "memory");            \
    } while (0)

    PREFETCH(0);
    PREFETCH(1);
    PREFETCH(2);

#pragma unroll 1
    for (int c = 0; c < NCHUNK; ++c) {
        if (c + 3 <= NCHUNK)
            asm volatile("cp.async.wait_group 2;" ::: "memory");
        else if (c + 2 == NCHUNK)
            asm volatile("cp.async.wait_group 1;" ::: "memory");
        else
            asm volatile("cp.async.wait_group 0;" ::: "memory");
        __syncthreads();

        if (c + 3 < NCHUNK) PREFETCH(c + 3);

        const uint32_t st = sbase + (c & (NSTAGE - 1)) * STAGE_BYTES;
        uint32_t afr[2][4][4], bfr[2][2][4];
#pragma unroll
        for (int ks = 0; ks < 2; ks++) {
#pragma unroll
            for (int mi = 0; mi < 4; mi++) ldsm4(afr[ks][mi], st + a_off[ks] + mi * 1024);
#pragma unroll
            for (int pi = 0; pi < 2; pi++) ldsm4(bfr[ks][pi], st + b_off[ks] + pi * 1024);
        }
#pragma unroll
        for (int ks = 0; ks < 2; ks++)
#pragma unroll
            for (int mi = 0; mi < 4; mi++)
#pragma unroll
                for (int ni = 0; ni < 4; ni++)
                    mma_bf16(acc[mi][ni],
                             afr[ks][mi][0], afr[ks][mi][1],
                             afr[ks][mi][2], afr[ks][mi][3],
                             bfr[ks][ni >> 1][(ni & 1) * 2],
                             bfr[ks][ni >> 1][(ni & 1) * 2 + 1]);
    }

    // ---- epilogue: exp((cos-1)/T), mask |s-t|<=1; row sums (+ col sums) ----
    const int rL = lane >> 2, cL = (lane & 3) * 2;
    const int row_base = t0 + warp_m * 64;
    const int col_base = s0 + warp_n * 32;
    const int posbase = b * TT;
    float rsum[4][2];
    float csum[4][2];
#pragma unroll
    for (int mi = 0; mi < 4; mi++) { rsum[mi][0] = 0.f; rsum[mi][1] = 0.f; }
#pragma unroll
    for (int ni = 0; ni < 4; ni++) { csum[ni][0] = 0.f; csum[ni][1] = 0.f; }

#pragma unroll
    for (int mi = 0; mi < 4; mi++)
#pragma unroll
        for (int ni = 0; ni < 4; ni++)
#pragma unroll
            for (int r = 0; r < 4; r++) {
                int t = row_base + mi * 16 + rL + (r >> 1) * 8;
                int s = col_base + ni * 8 + cL + (r & 1);
                float v = acc[mi][ni][r];
                int dd = s - t;
                if (dd == 1) g_pos[posbase + t] = v * 14.2857143f;
                float z = fmaf(v, 20.6099291f, -20.6099291f);  // (cos-1)*log2e/T
                float e;
                asm("ex2.approx.ftz.f32 %0, %1;" : "=f"(e) : "f"(z));
                bool keep = (unsigned)(dd + 1) > 2u;
                float em = keep ? e : 0.f;
                rsum[mi][r >> 1] += em;
                csum[ni][r & 1]  += em;
            }

    // row sums: reduce over the 4 lanes sharing each row (lane bits 0,1)
    const int rslot = tj * 4 + warp_n;
#pragma unroll
    for (int mi = 0; mi < 4; mi++)
#pragma unroll
        for (int h = 0; h < 2; h++) {
            float x = rsum[mi][h];
            x += __shfl_xor_sync(0xffffffffu, x, 1);
            x += __shfl_xor_sync(0xffffffffu, x, 2);
            if ((lane & 3) == 0)
                g_S48[rslot][posbase + row_base + mi * 16 + rL + h * 8] = x;
        }

    // col sums (mirror), full tiles only: reduce over lane bits 2,3,4 (rows)
    if (is_full) {
        const int cslot = 32 + ti * 2 + warp_m;
#pragma unroll
        for (int ni = 0; ni < 4; ni++)
#pragma unroll
            for (int p = 0; p < 2; p++) {
                float x = csum[ni][p];
                x += __shfl_xor_sync(0xffffffffu, x, 4);
                x += __shfl_xor_sync(0xffffffffu, x, 8);
                x += __shfl_xor_sync(0xffffffffu, x, 16);
                if ((lane & 28) == 0)
                    g_S48[cslot][posbase + col_base + ni * 8 + (lane & 3) * 2 + p] = x;
            }
    }
}

// ---------------------------------------------------------------------------
// Kernel 3a: per-anchor loss over 48 partial slots, 64-block parallel reduce.
// ---------------------------------------------------------------------------
__global__ __launch_bounds__(256) void loss_kernel() {
    const float M = 14.285714285714286f;   // 1/0.07
    int tid = threadIdx.x;
    int idx = blockIdx.x * 256 + tid;      // one anchor per thread
    float acc = 0.f;
    int tt = idx & (TT - 1);
    if (tt != 0 && tt != TT - 1) {
        float S = 0.f;
#pragma unroll
        for (int p = 0; p < 48; p++) S += g_S48[p][idx];
        float pos = g_pos[idx];
        acc = logf(expf(pos - M) + S) + M - pos;
    }
    __shared__ float sm[256];
    sm[tid] = acc;
    __syncthreads();
    for (int o = 128; o; o >>= 1) {
        if (tid < o) sm[tid] += sm[tid + o];
        __syncthreads();
    }
    if (tid == 0) g_part[blockIdx.x] = sm[0];
}

__global__ __launch_bounds__(64) void final_kernel(float* __restrict__ out) {
    int tid = threadIdx.x;
    __shared__ float sm[64];
    sm[tid] = g_part[tid];
    __syncthreads();
    for (int o = 32; o; o >>= 1) {
        if (tid < o) sm[tid] += sm[tid + o];
        __syncthreads();
    }
    if (tid == 0) out[0] = sm[0] / (float)(BB * (TT - 2));
}

// ---------------------------------------------------------------------------
extern "C" void kernel_launch(void* const* d_in, const int* in_sizes, int n_in,
                              void* d_out, int out_size) {
    const float* features = (const float*)d_in[0];
    float* out = (float*)d_out;

    cudaFuncSetAttribute(gram_kernel,
                         cudaFuncAttributeMaxDynamicSharedMemorySize,
                         NSTAGE * STAGE_BYTES);

    norm_kernel<<<BB * TT / 16, 256>>>(features);
    gram_kernel<<<dim3(36, BB), 256, NSTAGE * STAGE_BYTES>>>();
    loss_kernel<<<64, 256>>>();
    final_kernel<<<1, 64>>>(out);
}